// round 17
// baseline (speedup 1.0000x reference)
#include <cuda_runtime.h>

// PlasticSynapse: out = clip(baseline*a + w*(1-a) + R*|kappa|*(post*pre + s*noise), 0, 1)
// Shapes: w,noise,out: [B=64, OUT=1024, IN=1024]; baseline,kappa: [OUT,IN];
//         R: [B]; pre: [B,IN]; post: [B,OUT].
// HBM-bound elementwise: 768 MiB compulsory traffic (verified minimal).
//
// FINAL (locked). Experiment history:
//   R9  (256thr, 1x f4, stcs):  115.1us @ 87.4% DRAM
//   R10 (4x f4 strided/thread): 122.9us FAILED (regs 44, occ 54%)
//   R11 (128thr, 1x f4, stcs):  114.9us @ 87.1% DRAM, occ 85%
//   R12 (st.global.wt):         118.3us FAILED (loses L2 write coalescing)
//   R14 (2x f4 adjacent):       127.1us FAILED (intra-warp coalescing broken)
//   R16 (= R11):                114.8us @ 87.4% DRAM  <- BEST, confirmed
// Conclusion: one warp-contiguous float4 per thread + __ldcs streams +
// L2-resident baseline/kappa sits at the 2:1 read/write mixed-stream DRAM
// controller ceiling (~6.9 TB/s, 87% +/- run variance). Traffic is compulsory,
// coalescing perfect, all SM pipes slack. Path-independent (LTS cap), so no
// TMA/instruction-level change can move it. Locked.

#define B_   64
#define OUT_ 1024
#define IN_  1024
#define IN4_ (IN_ / 4)          // 256 float4 per row
#define TOTAL4 ((B_ * OUT_ * IN_) / 4)
#define ALPHA_W   0.01f
#define ONE_M_A   0.99f
#define SIGMA_W   0.14142135623730953f

__global__ __launch_bounds__(128)
void plastic_synapse_kernel(const float4* __restrict__ w,
                            const float4* __restrict__ baseline,
                            const float*  __restrict__ R,
                            const float4* __restrict__ pre,
                            const float*  __restrict__ post,
                            const float4* __restrict__ kappa,
                            const float4* __restrict__ noise,
                            float4*       __restrict__ out)
{
    const int idx = blockIdx.x * blockDim.x + threadIdx.x;   // float4 index
    // idx = ((b * OUT_) + o) * IN4_ + i4 ; all powers of two.
    const int i4 = idx & (IN4_ - 1);
    const int o  = (idx >> 8) & (OUT_ - 1);
    const int b  = idx >> 18;

    // Streamed (read-once) operands: evict-first, front-batched.
    const float4 w4 = __ldcs(&w[idx]);
    const float4 n4 = __ldcs(&noise[idx]);

    // Reused operands: L2-resident (8 MiB total), default caching.
    const int oi = o * IN4_ + i4;
    const float4 bl = __ldg(&baseline[oi]);
    const float4 kp = __ldg(&kappa[oi]);
    const float4 pr = __ldg(&pre[b * IN4_ + i4]);
    const float  r  = __ldg(&R[b]);
    const float  p  = __ldg(&post[b * OUT_ + o]);

    float4 res;
    {
        float plas = r * fabsf(kp.x) * fmaf(SIGMA_W, n4.x, p * pr.x);
        res.x = __saturatef(fmaf(bl.x, ALPHA_W, fmaf(w4.x, ONE_M_A, plas)));
    }
    {
        float plas = r * fabsf(kp.y) * fmaf(SIGMA_W, n4.y, p * pr.y);
        res.y = __saturatef(fmaf(bl.y, ALPHA_W, fmaf(w4.y, ONE_M_A, plas)));
    }
    {
        float plas = r * fabsf(kp.z) * fmaf(SIGMA_W, n4.z, p * pr.z);
        res.z = __saturatef(fmaf(bl.z, ALPHA_W, fmaf(w4.z, ONE_M_A, plas)));
    }
    {
        float plas = r * fabsf(kp.w) * fmaf(SIGMA_W, n4.w, p * pr.w);
        res.w = __saturatef(fmaf(bl.w, ALPHA_W, fmaf(w4.w, ONE_M_A, plas)));
    }

    __stcs(&out[idx], res);
}

extern "C" void kernel_launch(void* const* d_in, const int* in_sizes, int n_in,
                              void* d_out, int out_size)
{
    // metadata order: w, baseline, R, pre, post, kappa, noise
    const float4* w        = (const float4*)d_in[0];
    const float4* baseline = (const float4*)d_in[1];
    const float*  R        = (const float*) d_in[2];
    const float4* pre      = (const float4*)d_in[3];
    const float*  post     = (const float*) d_in[4];
    const float4* kappa    = (const float4*)d_in[5];
    const float4* noise    = (const float4*)d_in[6];
    float4*       out      = (float4*)d_out;

    const int threads = 128;
    const int blocks  = TOTAL4 / threads;   // 131,072 blocks

    plastic_synapse_kernel<<<blocks, threads>>>(w, baseline, R, pre, post,
                                                kappa, noise, out);
}